// round 3
// baseline (speedup 1.0000x reference)
#include <cuda_runtime.h>

// DCT compression: per 8x8 block 2D DCT (cos basis with PI=3.1415), diagonal
// norm, zigzag channel scatter, 1/Q quant scale. Single fused kernel.
//
// R3: revert cp.async staging (R2 regression: LSU/L1-bound). Direct LDG.128
// row streaming + packed fma.rn.f32x2 (halves fma-pipe instrs) +
// launch_bounds(128,5) for ~100 regs -> 5 CTAs/SM to hide DRAM latency.
//
// Input : x (32, 3, 512, 512) f32
// Output: (32, 192, 64, 64) f32, out[b, c*64 + z(a,u), hb, wb]

#define PI_A 3.1415f

typedef unsigned long long ull;

__device__ __forceinline__ ull pk2(float lo, float hi) {
    ull r; asm("mov.b64 %0, {%1, %2};" : "=l"(r) : "f"(lo), "f"(hi)); return r;
}
__device__ __forceinline__ void upk2(float& lo, float& hi, ull v) {
    asm("mov.b64 {%0, %1}, %2;" : "=f"(lo), "=f"(hi) : "l"(v));
}
__device__ __forceinline__ ull fma2(ull a, ull b, ull c) {
    ull d; asm("fma.rn.f32x2 %0, %1, %2, %3;" : "=l"(d) : "l"(a), "l"(b), "l"(c)); return d;
}
__device__ __forceinline__ ull mul2(ull a, ull b) {
    ull d; asm("mul.rn.f32x2 %0, %1, %2;" : "=l"(d) : "l"(a), "l"(b)); return d;
}

__constant__ float c_TL[64] = {
    16,11,10,16,24,40,51,61,
    12,12,14,19,26,58,60,55,
    14,13,16,24,40,57,69,56,
    14,17,22,29,51,87,80,62,
    18,22,37,56,68,109,103,77,
    24,35,55,64,81,104,113,92,
    49,64,78,87,103,121,120,101,
    72,92,95,98,112,100,103,99};

__constant__ float c_QC[64] = {
    17,18,24,47,99,99,99,99,
    18,21,26,66,99,99,99,99,
    24,26,56,99,99,99,99,99,
    47,66,99,99,99,99,99,99,
    99,99,99,99,99,99,99,99,
    99,99,99,99,99,99,99,99,
    99,99,99,99,99,99,99,99,
    99,99,99,99,99,99,99,99};

// Closed form of the module's zigzag() p[y][x]:
//   for s=x+y<8: p = tri(s+1) - (s odd ? y : x) - 1
//   else       : p = 63 - p[7-y][7-x]
__device__ __forceinline__ int zz_p(int y, int x) {
    int s = x + y;
    if (s < 8) {
        int t = (s + 1) * (s + 2) / 2;
        return (s & 1) ? (t - y - 1) : (t - x - 1);
    }
    int yy = 7 - y, xx = 7 - x;
    int s2 = xx + yy;
    int t = (s2 + 1) * (s2 + 2) / 2;
    return 63 - ((s2 & 1) ? (t - yy - 1) : (t - xx - 1));
}

__global__ void __launch_bounds__(128, 5)
dct_kernel(const float* __restrict__ x, float* __restrict__ out) {
    __shared__ float  sM[64];      // sM[freq*8 + spatial]; aliased as float2 pairs in stage 2
    __shared__ float2 sMd[64];     // duplicated (m, m) for stage-1 broadcast
    __shared__ float  sScale[64];  // norm(a,u) / Qtable[zigzag(a,u)]
    __shared__ int    sChan[64];   // zigzag channel for coef index a*8+u

    const int  tid  = threadIdx.x;
    const long gid0 = (long)blockIdx.x * 128;
    const int  c    = (int)((gid0 >> 12) % 3);   // c constant within CTA

    if (tid < 64) {
        int fi = tid >> 3, j = tid & 7;
        float ap = ((float)fi + 0.5f) * PI_A;
        float m = cosf(ap * ((float)j * 0.125f));
        sM[tid]  = m;
        sMd[tid] = make_float2(m, m);
    } else {
        int i = tid - 64;
        int a = i >> 3, u = i & 7;
        int ch = zz_p(u, a);                     // z = pattern.T => z[a*8+u] = p[u][a]
        sChan[i] = ch;
        float nrm = ((a == 0) || (u == 0)) ? 0.17677669529663687f : 0.25f;
        float q   = (c == 0) ? c_TL[ch] : c_QC[ch];
        sScale[i] = nrm / q;
    }
    __syncthreads();

    const long gid = gid0 + tid;
    const int  wb  = (int)(gid & 63);
    const int  hb  = (int)((gid >> 6) & 63);
    const int  bc  = (int)(gid >> 12);           // b*3 + c

    const float* src = x + (((long)bc * 512 + hb * 8) * 512 + wb * 8);

    // ---- Stage 1 (row-streamed): accP[a][p] += M[a][y] * rowPair[p] ----
    ull accP[8][4];
#pragma unroll
    for (int a = 0; a < 8; ++a)
#pragma unroll
        for (int p = 0; p < 4; ++p) accP[a][p] = 0ull;

#pragma unroll
    for (int y = 0; y < 8; ++y) {
        float4 q0 = *(const float4*)(src + (long)y * 512);
        float4 q1 = *(const float4*)(src + (long)y * 512 + 4);
        ull rp0 = pk2(q0.x, q0.y);
        ull rp1 = pk2(q0.z, q0.w);
        ull rp2 = pk2(q1.x, q1.y);
        ull rp3 = pk2(q1.z, q1.w);
#pragma unroll
        for (int a = 0; a < 8; ++a) {
            ull m2 = *(const ull*)&sMd[a * 8 + y];      // LDS.64 broadcast (m,m)
            accP[a][0] = fma2(m2, rp0, accP[a][0]);
            accP[a][1] = fma2(m2, rp1, accP[a][1]);
            accP[a][2] = fma2(m2, rp2, accP[a][2]);
            accP[a][3] = fma2(m2, rp3, accP[a][3]);
        }
    }

    // ---- Stage 2: coef[a][u] = hsum_p(accP[a][p] * Mpair[u][p]); scale; scatter ----
    const float2* Mp = (const float2*)sM;        // pairwise (M[u][2p], M[u][2p+1])
    float* dst = out + ((long)bc << 18) + (hb << 6) + wb;
#pragma unroll
    for (int u = 0; u < 8; ++u) {
        ull mu0 = *(const ull*)&Mp[u * 4 + 0];
        ull mu1 = *(const ull*)&Mp[u * 4 + 1];
        ull mu2 = *(const ull*)&Mp[u * 4 + 2];
        ull mu3 = *(const ull*)&Mp[u * 4 + 3];
#pragma unroll
        for (int a = 0; a < 8; ++a) {
            ull s2 = mul2(accP[a][0], mu0);
            s2 = fma2(accP[a][1], mu1, s2);
            s2 = fma2(accP[a][2], mu2, s2);
            s2 = fma2(accP[a][3], mu3, s2);
            float e, o; upk2(e, o, s2);
            int i = a * 8 + u;
            dst[(long)sChan[i] << 12] = (e + o) * sScale[i];
        }
    }
}

extern "C" void kernel_launch(void* const* d_in, const int* in_sizes, int n_in,
                              void* d_out, int out_size) {
    const float* x   = (const float*)d_in[0];
    float*       out = (float*)d_out;
    // 32*3*64*64 = 393216 blocks, 128 threads (blocks) per CTA -> 3072 CTAs
    dct_kernel<<<3072, 128>>>(x, out);
}

// round 5
// speedup vs baseline: 1.1934x; 1.1934x over previous
#include <cuda_runtime.h>

// DCT compression: per 8x8 block 2D DCT (cos basis with PI=3.1415), diagonal
// norm, zigzag channel scatter, 1/Q quant scale. Single fused kernel.
//
// R5: R4 fixed for ptxas: L2::evict_last on ld.global.nc requires 256-bit
// form on sm_103a -> use ld.global.nc.L2::evict_last.v4.b64 (one LDG.256
// per 8-float block row; 8 loads/thread instead of 16). Stores st.global.cs
// (evict-first) so the output stream doesn't evict the pinned input.
// Stage-2 fused per output row 'a' -> ~105 live regs, 4 CTAs/SM.
//
// Input : x (32, 3, 512, 512) f32
// Output: (32, 192, 64, 64) f32, out[b, c*64 + z(a,u), hb, wb]

#define PI_A 3.1415f

typedef unsigned long long ull;

__constant__ float c_TL[64] = {
    16,11,10,16,24,40,51,61,
    12,12,14,19,26,58,60,55,
    14,13,16,24,40,57,69,56,
    14,17,22,29,51,87,80,62,
    18,22,37,56,68,109,103,77,
    24,35,55,64,81,104,113,92,
    49,64,78,87,103,121,120,101,
    72,92,95,98,112,100,103,99};

__constant__ float c_QC[64] = {
    17,18,24,47,99,99,99,99,
    18,21,26,66,99,99,99,99,
    24,26,56,99,99,99,99,99,
    47,66,99,99,99,99,99,99,
    99,99,99,99,99,99,99,99,
    99,99,99,99,99,99,99,99,
    99,99,99,99,99,99,99,99,
    99,99,99,99,99,99,99,99};

// Closed form of the module's zigzag() p[y][x]:
//   for s=x+y<8: p = tri(s+1) - (s odd ? y : x) - 1
//   else       : p = 63 - p[7-y][7-x]
__device__ __forceinline__ int zz_p(int y, int x) {
    int s = x + y;
    if (s < 8) {
        int t = (s + 1) * (s + 2) / 2;
        return (s & 1) ? (t - y - 1) : (t - x - 1);
    }
    int yy = 7 - y, xx = 7 - x;
    int s2 = xx + yy;
    int t = (s2 + 1) * (s2 + 2) / 2;
    return 63 - ((s2 & 1) ? (t - yy - 1) : (t - xx - 1));
}

// One 256-bit load = one full 8-float block row, L2 evict_last (keep resident).
__device__ __forceinline__ void ldg256_keep(const float* p, float* r8) {
    ull a, b, c, d;
    asm volatile("ld.global.nc.L2::evict_last.v4.b64 {%0,%1,%2,%3}, [%4];"
                 : "=l"(a), "=l"(b), "=l"(c), "=l"(d) : "l"(p));
    asm("mov.b64 {%0, %1}, %2;" : "=f"(r8[0]), "=f"(r8[1]) : "l"(a));
    asm("mov.b64 {%0, %1}, %2;" : "=f"(r8[2]), "=f"(r8[3]) : "l"(b));
    asm("mov.b64 {%0, %1}, %2;" : "=f"(r8[4]), "=f"(r8[5]) : "l"(c));
    asm("mov.b64 {%0, %1}, %2;" : "=f"(r8[6]), "=f"(r8[7]) : "l"(d));
}

__device__ __forceinline__ void stg_stream(float* p, float v) {
    asm volatile("st.global.cs.f32 [%0], %1;" :: "l"(p), "f"(v) : "memory");
}

__global__ void __launch_bounds__(128, 4)
dct_kernel(const float* __restrict__ x, float* __restrict__ out) {
    __shared__ float sM[64];      // sM[freq*8 + spatial]
    __shared__ float sScale[64];  // norm(a,u) / Qtable[zigzag(a,u)]
    __shared__ int   sChan[64];   // zigzag channel for coef index a*8+u

    const int  tid  = threadIdx.x;
    const long gid0 = (long)blockIdx.x * 128;
    const int  c    = (int)((gid0 >> 12) % 3);   // c constant within CTA

    if (tid < 64) {
        int fi = tid >> 3, j = tid & 7;
        float ap = ((float)fi + 0.5f) * PI_A;
        sM[tid] = cosf(ap * ((float)j * 0.125f));
    } else {
        int i = tid - 64;
        int a = i >> 3, u = i & 7;
        int ch = zz_p(u, a);                     // z = pattern.T => z[a*8+u] = p[u][a]
        sChan[i] = ch;
        float nrm = ((a == 0) || (u == 0)) ? 0.17677669529663687f : 0.25f;
        float q   = (c == 0) ? c_TL[ch] : c_QC[ch];
        sScale[i] = nrm / q;
    }
    __syncthreads();

    const long gid = gid0 + tid;
    const int  wb  = (int)(gid & 63);
    const int  hb  = (int)((gid >> 6) & 63);
    const int  bc  = (int)(gid >> 12);           // b*3 + c

    const float* src = x + (((long)bc * 512 + hb * 8) * 512 + wb * 8);

    // ---- Front-batch the full 8x8 block (8 LDG.256 in flight, L2 keep) ----
    float blk[8][8];
#pragma unroll
    for (int y = 0; y < 8; ++y)
        ldg256_keep(src + (long)y * 512, blk[y]);

    // ---- Fused: for each output row a, compute tmp_a then 8 coefs + stores ----
    float* dst = out + ((long)bc << 18) + (hb << 6) + wb;
#pragma unroll
    for (int a = 0; a < 8; ++a) {
        float tmp_a[8];
#pragma unroll
        for (int xx = 0; xx < 8; ++xx) {
            float acc = sM[a * 8] * blk[0][xx];
#pragma unroll
            for (int y = 1; y < 8; ++y)
                acc = fmaf(sM[a * 8 + y], blk[y][xx], acc);
            tmp_a[xx] = acc;
        }
#pragma unroll
        for (int u = 0; u < 8; ++u) {
            float s = tmp_a[0] * sM[u * 8];
#pragma unroll
            for (int xx = 1; xx < 8; ++xx)
                s = fmaf(tmp_a[xx], sM[u * 8 + xx], s);
            int i = a * 8 + u;
            stg_stream(dst + ((long)sChan[i] << 12), s * sScale[i]);
        }
    }
}

extern "C" void kernel_launch(void* const* d_in, const int* in_sizes, int n_in,
                              void* d_out, int out_size) {
    const float* x   = (const float*)d_in[0];
    float*       out = (float*)d_out;
    // 32*3*64*64 = 393216 blocks, 128 threads (blocks) per CTA -> 3072 CTAs
    dct_kernel<<<3072, 128>>>(x, out);
}

// round 7
// speedup vs baseline: 2.0901x; 1.7514x over previous
#include <cuda_runtime.h>

// DCT compression: per 8x8 block 2D DCT (cos basis with PI=3.1415), diagonal
// norm, zigzag channel scatter, 1/Q quant scale. Single fused kernel.
//
// R7 (= R6 build-fixed): all multipliers (cos basis, norm/quant scales) are
// compile-time constants -> constexpr tables folded into FFMA-immediate form
// (rt_SMSP=1, 2x throughput of 3-reg FFMA). Table is a LOCAL constexpr in the
// device function (no --expt-relaxed-constexpr needed). No shared memory, no
// LDS, no syncthreads. Zigzag channels are immediate STG offsets. Plain
// R1-style loads/stores (cache hints measured as regressions in R4/R5).
//
// Input : x (32, 3, 512, 512) f32
// Output: (32, 192, 64, 64) f32, out[b, c*64 + z(a,u), hb, wb]

// ---- constexpr math (compile-time only) ----
__host__ __device__ constexpr double cc_cos(double x) {
    const double TWO_PI = 6.283185307179586476925286766559;
    const double PI_D   = 3.14159265358979323846;
    while (x >  PI_D) x -= TWO_PI;
    while (x < -PI_D) x += TWO_PI;
    double x2 = x * x, t = 1.0, s = 1.0;
    for (int n = 1; n <= 16; ++n) { t *= -x2 / ((2.0 * n - 1.0) * (2.0 * n)); s += t; }
    return s;
}

// Mirrors the module: arg = f32((f+0.5)*3.1415f) * f32(j*0.125f), cos of that.
__host__ __device__ constexpr float cc_cm(int f, int j) {
    float ap = (float)(f + 0.5f) * 3.1415f;
    float bj = (float)j * 0.125f;
    return (float)cc_cos((double)(ap * bj));
}

// Module's zigzag() p[y][x], closed form.
__host__ __device__ constexpr int zz_p(int y, int x) {
    int s = x + y;
    if (s < 8) {
        int t = (s + 1) * (s + 2) / 2;
        return (s & 1) ? (t - y - 1) : (t - x - 1);
    }
    int yy = 7 - y, xx = 7 - x;
    int s2 = xx + yy;
    int t = (s2 + 1) * (s2 + 2) / 2;
    return 63 - ((s2 & 1) ? (t - yy - 1) : (t - xx - 1));
}

struct Tabs {
    float cm[8][8];     // cos basis
    float scl[2][8][8]; // [luma?0:1][a][u] = norm(a,u)/Q[ch]
    int   ch[8][8];     // zigzag channel for (a,u)
};

__host__ __device__ constexpr Tabs make_tabs() {
    constexpr float TLQ[64] = {
        16,11,10,16,24,40,51,61, 12,12,14,19,26,58,60,55,
        14,13,16,24,40,57,69,56, 14,17,22,29,51,87,80,62,
        18,22,37,56,68,109,103,77, 24,35,55,64,81,104,113,92,
        49,64,78,87,103,121,120,101, 72,92,95,98,112,100,103,99};
    constexpr float CQQ[64] = {
        17,18,24,47,99,99,99,99, 18,21,26,66,99,99,99,99,
        24,26,56,99,99,99,99,99, 47,66,99,99,99,99,99,99,
        99,99,99,99,99,99,99,99, 99,99,99,99,99,99,99,99,
        99,99,99,99,99,99,99,99, 99,99,99,99,99,99,99,99};
    Tabs t{};
    for (int f = 0; f < 8; ++f)
        for (int j = 0; j < 8; ++j)
            t.cm[f][j] = cc_cm(f, j);
    for (int a = 0; a < 8; ++a)
        for (int u = 0; u < 8; ++u) {
            int ch = zz_p(u, a);                // z = pattern.T
            t.ch[a][u] = ch;
            float nrm = ((a == 0) || (u == 0)) ? 0.17677669529663687f : 0.25f;
            t.scl[0][a][u] = nrm / TLQ[ch];
            t.scl[1][a][u] = nrm / CQQ[ch];
        }
    return t;
}

template<int LC>
__device__ __forceinline__ void dct_body(const float* __restrict__ src,
                                         float* __restrict__ dst) {
    constexpr Tabs T = make_tabs();   // local constexpr: fully folded, no memory

    // Front-batch the full 8x8 block (16 LDG.128 in flight)
    float blk[8][8];
#pragma unroll
    for (int y = 0; y < 8; ++y) {
        float4 p0 = __ldg((const float4*)(src + (long)y * 512));
        float4 p1 = __ldg((const float4*)(src + (long)y * 512 + 4));
        blk[y][0] = p0.x; blk[y][1] = p0.y; blk[y][2] = p0.z; blk[y][3] = p0.w;
        blk[y][4] = p1.x; blk[y][5] = p1.y; blk[y][6] = p1.z; blk[y][7] = p1.w;
    }

#pragma unroll
    for (int a = 0; a < 8; ++a) {
        float tmp[8];
#pragma unroll
        for (int xx = 0; xx < 8; ++xx) {
            float acc = blk[0][xx] * T.cm[a][0];   // cm[a][0]==1 -> folds
#pragma unroll
            for (int y = 1; y < 8; ++y)
                acc = fmaf(blk[y][xx], T.cm[a][y], acc);   // FFMA-imm
            tmp[xx] = acc;
        }
#pragma unroll
        for (int u = 0; u < 8; ++u) {
            float s = tmp[0] * T.cm[u][0];          // ==tmp[0]
#pragma unroll
            for (int xx = 1; xx < 8; ++xx)
                s = fmaf(tmp[xx], T.cm[u][xx], s);  // FFMA-imm
            dst[(long)T.ch[a][u] << 12] = s * T.scl[LC][a][u];  // FMUL-imm + STG imm-offset
        }
    }
}

__global__ void __launch_bounds__(128, 5)
dct_kernel(const float* __restrict__ x, float* __restrict__ out) {
    const long gid = (long)blockIdx.x * 128 + threadIdx.x;
    const int  wb  = (int)(gid & 63);
    const int  hb  = (int)((gid >> 6) & 63);
    const int  bc  = (int)(gid >> 12);           // b*3 + c
    const int  c   = bc % 3;                     // uniform within CTA

    const float* src = x + (((long)bc * 512 + hb * 8) * 512 + wb * 8);
    float*       dst = out + ((long)bc << 18) + (hb << 6) + wb;

    if (c == 0) dct_body<0>(src, dst);
    else        dct_body<1>(src, dst);
}

extern "C" void kernel_launch(void* const* d_in, const int* in_sizes, int n_in,
                              void* d_out, int out_size) {
    const float* x   = (const float*)d_in[0];
    float*       out = (float*)d_out;
    // 32*3*64*64 = 393216 blocks, 128 threads (blocks) per CTA -> 3072 CTAs
    dct_kernel<<<3072, 128>>>(x, out);
}